// round 8
// baseline (speedup 1.0000x reference)
#include <cuda_runtime.h>
#include <cuda_bf16.h>
#include <math.h>

// ---------------- problem constants ----------------
#define BATCH   8
#define SEQ     2048
#define TOK     (BATCH*SEQ)      // 16384
#define DMODEL  128
#define EMB     256
#define NLAYERS 3
#define NHEADS  8
#define HEADDIM 64
#define DSTATE  64
#define DCONV   4
#define DINNER  (NHEADS*HEADDIM)             // 512
#define DIP     (2*DINNER + 2*DSTATE + NHEADS) // 1160
#define CDIM    (DINNER + 2*DSTATE)          // 640
#define NFEAT   15

// ---------------- device scratch ----------------
__device__ float g_w[16];
__device__ float g_xn[TOK*EMB];
__device__ float g_x [TOK*EMB];
__device__ float g_z [TOK*DIP];
__device__ float g_xbc[TOK*CDIM];
__device__ float2 g_dtA[TOK*NHEADS];   // (.x = dt, .y = dA)
__device__ float g_y [TOK*DINNER];
__device__ float g_h1[TOK*EMB];

// ---------------- helpers ----------------
__device__ __forceinline__ float blockReduceSum(float v) {
    __shared__ float red[32];
    int lane = threadIdx.x & 31;
    int wid  = threadIdx.x >> 5;
    int nw   = (blockDim.x + 31) >> 5;
    #pragma unroll
    for (int o = 16; o; o >>= 1) v += __shfl_xor_sync(0xffffffffu, v, o);
    __syncthreads();
    if (lane == 0) red[wid] = v;
    __syncthreads();
    float tot = 0.f;
    for (int i = 0; i < nw; ++i) tot += red[i];
    return tot;
}

__device__ __forceinline__ float siluf(float x) { return x / (1.f + expf(-x)); }

__device__ __forceinline__ void mma_tf32(float* d, const unsigned* a, unsigned b0, unsigned b1) {
    asm volatile(
        "mma.sync.aligned.m16n8k8.row.col.f32.tf32.tf32.f32 "
        "{%0,%1,%2,%3},{%4,%5,%6,%7},{%8,%9},{%0,%1,%2,%3};\n"
        : "+f"(d[0]), "+f"(d[1]), "+f"(d[2]), "+f"(d[3])
        : "r"(a[0]), "r"(a[1]), "r"(a[2]), "r"(a[3]), "r"(b0), "r"(b1));
}

__device__ __forceinline__ void tf32_split(float x, unsigned& hi, unsigned& lo) {
    unsigned h;
    asm("cvt.rna.tf32.f32 %0, %1;\n" : "=r"(h) : "f"(x));
    float r = x - __uint_as_float(h);
    unsigned l;
    asm("cvt.rna.tf32.f32 %0, %1;\n" : "=r"(l) : "f"(r));
    hi = h; lo = l;
}

// ---------------- K0: softmax of w_avg ----------------
__global__ void softmax_kernel(const float* __restrict__ wa, int n) {
    if (threadIdx.x == 0) {
        float mx = -1e30f;
        for (int i = 0; i < n; ++i) mx = fmaxf(mx, wa[i]);
        float s = 0.f;
        for (int i = 0; i < n; ++i) { float e = expf(wa[i] - mx); g_w[i] = e; s += e; }
        float inv = 1.f / s;
        for (int i = 0; i < n; ++i) g_w[i] *= inv;
    }
}

// ---------------- K1: weighted feature average + layernorm(128) ----------------
__global__ void __launch_bounds__(128) avg_ln_kernel(
    const float* __restrict__ feat, const float* __restrict__ lg,
    const float* __restrict__ lb) {
    int r = blockIdx.x;
    int d = threadIdx.x;
    float acc = 0.f;
    #pragma unroll
    for (int f = 0; f < NFEAT; ++f)
        acc = fmaf(g_w[f], feat[((size_t)f * TOK + r) * DMODEL + d], acc);
    float m = blockReduceSum(acc) * (1.f / DMODEL);
    float dv = acc - m;
    float var = blockReduceSum(dv * dv) * (1.f / DMODEL);
    g_xn[(size_t)r * DMODEL + d] = dv * rsqrtf(var + 1e-5f) * lg[d] + lb[d];
}

// ---------------- 3xTF32 GEMM v2: split-at-STS, fused row-norm pre-ops ----------------
// C = epi( sc_row * (pre(A)(MxK) @ W(KxN)) )
// PRE: 0 = plain A
//      1 = rmsnorm fusion: store x*prew[k], sc_row = rsqrt(mean x^2 + eps)
//      2 = gate fusion:    g = y*silu(z); store g*prew[k], sc_row = rsqrt(mean g^2 + eps)
// EPI: 0=none 1=+bias 2=gelu(x+bias) 3=+residual
// Tiles BM=128 BN=128 BK=32; 8 warps (4m x 2n); warp tile 32x64.
// Smem planes hold (hi,lo) tf32 pairs as float2; LDS.64 fetches both terms at once.
#define ASF2 36
#define BSF2 132
#define ASF2_ELEMS (128*ASF2)
#define BSF2_ELEMS (32*BSF2)
#define TG2_SMEM ((2*ASF2_ELEMS + 2*BSF2_ELEMS)*8)

template<int PRE, int EPI>
__global__ void __launch_bounds__(256, 1) tgemm2_kernel(
    const float* __restrict__ A, const float* __restrict__ Az,
    const float* __restrict__ W, const float* __restrict__ prew,
    const float* __restrict__ bias, const float* __restrict__ res,
    float* __restrict__ C, int M, int N, int K)
{
    extern __shared__ float2 sm2[];
    float2* As[2] = { sm2, sm2 + ASF2_ELEMS };
    float2* Bs[2] = { sm2 + 2*ASF2_ELEMS, sm2 + 2*ASF2_ELEMS + BSF2_ELEMS };
    __shared__ float s_sc[128];

    int tid = threadIdx.x;
    int n0 = blockIdx.x * 128;
    int m0 = blockIdx.y * 128;
    int wid = tid >> 5, lane = tid & 31;
    int wm = wid >> 1, wn = wid & 1;
    int m0w = wm * 32, n0w = wn * 64;
    int g = lane >> 2, q = lane & 3;

    float acc[2][8][4];
    #pragma unroll
    for (int mi = 0; mi < 2; ++mi)
        #pragma unroll
        for (int ni = 0; ni < 8; ++ni)
            #pragma unroll
            for (int c = 0; c < 4; ++c) acc[mi][ni][c] = 0.f;

    int ar = tid >> 1, ak = (tid & 1) * 16;    // A: 2 threads per row, 16 k each
    int bk = tid & 31, bn = (tid >> 5) * 16;   // B: 1 k-row per lane-id, 16 n per warp

    float row_ss = 0.f;
    float4 rA[4], rZ[4], rB[4];

    auto loadG = [&](int k0) {
        const float* ag = A + (size_t)(m0 + ar) * K + k0 + ak;
        #pragma unroll
        for (int j = 0; j < 4; ++j) rA[j] = *(const float4*)(ag + j * 4);
        if (PRE == 2) {
            const float* zg = Az + (size_t)(m0 + ar) * DIP + k0 + ak;
            #pragma unroll
            for (int j = 0; j < 4; ++j) rZ[j] = *(const float4*)(zg + j * 4);
        }
        const float* bg = W + (size_t)(k0 + bk) * N + n0 + bn;
        #pragma unroll
        for (int j = 0; j < 4; ++j) {
            int col = n0 + bn + j * 4;
            rB[j] = (col < N) ? *(const float4*)(bg + j * 4)
                              : make_float4(0.f, 0.f, 0.f, 0.f);
        }
    };

    auto sts = [&](int buf, int k0) {
        float2* ad = As[buf] + ar * ASF2 + ak;
        #pragma unroll
        for (int j = 0; j < 4; ++j) {
            float v[4] = { rA[j].x, rA[j].y, rA[j].z, rA[j].w };
            if (PRE == 1) {
                const float* wv = prew + k0 + ak + j * 4;
                #pragma unroll
                for (int e = 0; e < 4; ++e) {
                    float x = v[e];
                    row_ss = fmaf(x, x, row_ss);
                    v[e] = x * wv[e];
                }
            } else if (PRE == 2) {
                float zz[4] = { rZ[j].x, rZ[j].y, rZ[j].z, rZ[j].w };
                const float* wv = prew + k0 + ak + j * 4;
                #pragma unroll
                for (int e = 0; e < 4; ++e) {
                    float gg = v[e] * siluf(zz[e]);
                    row_ss = fmaf(gg, gg, row_ss);
                    v[e] = gg * wv[e];
                }
            }
            unsigned h[4], l[4];
            #pragma unroll
            for (int e = 0; e < 4; ++e) tf32_split(v[e], h[e], l[e]);
            uint4* dst = (uint4*)(ad + j * 4);
            dst[0] = make_uint4(h[0], l[0], h[1], l[1]);
            dst[1] = make_uint4(h[2], l[2], h[3], l[3]);
        }
        float2* bd = Bs[buf] + bk * BSF2 + bn;
        #pragma unroll
        for (int j = 0; j < 4; ++j) {
            float v[4] = { rB[j].x, rB[j].y, rB[j].z, rB[j].w };
            unsigned h[4], l[4];
            #pragma unroll
            for (int e = 0; e < 4; ++e) tf32_split(v[e], h[e], l[e]);
            uint4* dst = (uint4*)(bd + j * 4);
            dst[0] = make_uint4(h[0], l[0], h[1], l[1]);
            dst[1] = make_uint4(h[2], l[2], h[3], l[3]);
        }
    };

    int nk = K >> 5;
    loadG(0);
    sts(0, 0);
    loadG(32);
    __syncthreads();

    for (int kb = 0; kb < nk; ++kb) {
        const float2* Ab = As[kb & 1];
        const float2* Bb = Bs[kb & 1];
        #pragma unroll
        for (int ks = 0; ks < 4; ++ks) {
            int kq = ks * 8;
            unsigned ah[2][4], al[2][4];
            #pragma unroll
            for (int mi = 0; mi < 2; ++mi) {
                const float2* ab = Ab + (m0w + mi * 16 + g) * ASF2 + kq + q;
                float2 t0 = ab[0];
                float2 t1 = ab[8 * ASF2];
                float2 t2 = ab[4];
                float2 t3 = ab[8 * ASF2 + 4];
                ah[mi][0] = __float_as_uint(t0.x); al[mi][0] = __float_as_uint(t0.y);
                ah[mi][1] = __float_as_uint(t1.x); al[mi][1] = __float_as_uint(t1.y);
                ah[mi][2] = __float_as_uint(t2.x); al[mi][2] = __float_as_uint(t2.y);
                ah[mi][3] = __float_as_uint(t3.x); al[mi][3] = __float_as_uint(t3.y);
            }
            #pragma unroll
            for (int ni = 0; ni < 8; ++ni) {
                const float2* bb = Bb + (kq + q) * BSF2 + n0w + ni * 8 + g;
                float2 s0 = bb[0];
                float2 s1 = bb[4 * BSF2];
                unsigned bh0 = __float_as_uint(s0.x), bl0 = __float_as_uint(s0.y);
                unsigned bh1 = __float_as_uint(s1.x), bl1 = __float_as_uint(s1.y);
                mma_tf32(acc[0][ni], al[0], bh0, bh1);
                mma_tf32(acc[1][ni], al[1], bh0, bh1);
                mma_tf32(acc[0][ni], ah[0], bl0, bl1);
                mma_tf32(acc[1][ni], ah[1], bl0, bl1);
                mma_tf32(acc[0][ni], ah[0], bh0, bh1);
                mma_tf32(acc[1][ni], ah[1], bh0, bh1);
            }
        }
        if (kb + 1 < nk) {
            __syncthreads();
            sts((kb + 1) & 1, (kb + 1) * 32);
            if (kb + 2 < nk) loadG((kb + 2) * 32);
            __syncthreads();
        }
    }

    if (PRE > 0) {
        float tot = row_ss + __shfl_xor_sync(0xffffffffu, row_ss, 1);
        if ((tid & 1) == 0) s_sc[ar] = rsqrtf(tot * (1.f / (float)K) + 1e-5f);
        __syncthreads();
    }

    #pragma unroll
    for (int mi = 0; mi < 2; ++mi) {
        #pragma unroll
        for (int ni = 0; ni < 8; ++ni) {
            int col = n0 + n0w + ni * 8 + 2 * q;
            if (col >= N) continue;
            #pragma unroll
            for (int half = 0; half < 2; ++half) {
                int lrow = m0w + mi * 16 + g + half * 8;
                int row = m0 + lrow;
                float sc = (PRE > 0) ? s_sc[lrow] : 1.f;
                float v0 = sc * acc[mi][ni][half * 2 + 0];
                float v1 = sc * acc[mi][ni][half * 2 + 1];
                if (EPI == 1) { v0 += bias[col]; v1 += bias[col + 1]; }
                else if (EPI == 2) {
                    v0 += bias[col]; v1 += bias[col + 1];
                    v0 = 0.5f * v0 * (1.f + erff(v0 * 0.70710678118654752f));
                    v1 = 0.5f * v1 * (1.f + erff(v1 * 0.70710678118654752f));
                } else if (EPI == 3) {
                    const float* rp = res + (size_t)row * N + col;
                    v0 += rp[0]; v1 += rp[1];
                }
                *(float2*)(C + (size_t)row * N + col) = make_float2(v0, v1);
            }
        }
    }
}

// ---------------- conv (depthwise causal, DCONV=4) + silu, plus packed dt/dA ----------------
__global__ void __launch_bounds__(256) conv_kernel(
    const float* __restrict__ cw, const float* __restrict__ cb,
    const float* __restrict__ dtb, const float* __restrict__ alog) {
    int r = blockIdx.x;
    int b = r >> 11, t = r & 2047;
    for (int c = threadIdx.x; c < CDIM; c += 256) {
        float acc = cb[c];
        #pragma unroll
        for (int k = 0; k < DCONV; ++k) {
            int tt = t - (DCONV - 1) + k;
            if (tt >= 0)
                acc = fmaf(g_z[((size_t)(b * SEQ + tt)) * DIP + DINNER + c], cw[c * DCONV + k], acc);
        }
        g_xbc[(size_t)r * CDIM + c] = siluf(acc);
    }
    if (threadIdx.x < NHEADS) {
        int hh = threadIdx.x;
        float v = g_z[(size_t)r * DIP + (DIP - NHEADS) + hh] + dtb[hh];
        float dt = (v > 20.f) ? v : log1pf(expf(v));
        float dA = expf(-dt * expf(alog[hh]));
        g_dtA[r * NHEADS + hh] = make_float2(dt, dA);
    }
}

// ---------------- selective scan: warp-autonomous register version (R5, passing) ----------------
#define SDEPTH 4

__global__ void __launch_bounds__(256) scan_kernel(const float* __restrict__ Dp) {
    int pz = blockIdx.x;
    int h  = blockIdx.y;
    int b  = blockIdx.z;
    int tid = threadIdx.x;
    int w = tid >> 5, lane = tid & 31;
    int p_sub = lane >> 3;
    int n_sub = lane & 7;
    int p = pz * 32 + w * 4 + p_sub;

    const float* base = g_xbc + (size_t)b * SEQ * CDIM;
    const float2* dbase = g_dtA + (size_t)b * SEQ * NHEADS + h;
    float* ybase = g_y + (size_t)b * SEQ * DINNER + h * HEADDIM + p;
    float Dv = Dp[h];

    float hs[8];
    #pragma unroll
    for (int j = 0; j < 8; ++j) hs[j] = 0.f;

    float4 Bb[SDEPTH][2], Cb[SDEPTH][2];
    float  xb[SDEPTH];
    float2 db[SDEPTH];

    const int boff = DINNER + n_sub * 8;
    const int coff = DINNER + DSTATE + n_sub * 8;
    const int xoff = h * HEADDIM + p;

    #pragma unroll
    for (int s = 0; s < SDEPTH; ++s) {
        const float* row = base + (size_t)s * CDIM;
        Bb[s][0] = *(const float4*)(row + boff);
        Bb[s][1] = *(const float4*)(row + boff + 4);
        Cb[s][0] = *(const float4*)(row + coff);
        Cb[s][1] = *(const float4*)(row + coff + 4);
        xb[s] = row[xoff];
        db[s] = dbase[(size_t)s * NHEADS];
    }

    for (int t0 = 0; t0 < SEQ; t0 += SDEPTH) {
        #pragma unroll
        for (int s = 0; s < SDEPTH; ++s) {
            int t = t0 + s;
            float dtv = db[s].x, dAv = db[s].y;
            float xv = xb[s];
            float cbm = dtv * xv;
            float4 B0 = Bb[s][0], B1 = Bb[s][1];
            float4 C0 = Cb[s][0], C1 = Cb[s][1];
            float acc;
            hs[0] = fmaf(hs[0], dAv, cbm * B0.x); acc = hs[0] * C0.x;
            hs[1] = fmaf(hs[1], dAv, cbm * B0.y); acc = fmaf(hs[1], C0.y, acc);
            hs[2] = fmaf(hs[2], dAv, cbm * B0.z); acc = fmaf(hs[2], C0.z, acc);
            hs[3] = fmaf(hs[3], dAv, cbm * B0.w); acc = fmaf(hs[3], C0.w, acc);
            hs[4] = fmaf(hs[4], dAv, cbm * B1.x); acc = fmaf(hs[4], C1.x, acc);
            hs[5] = fmaf(hs[5], dAv, cbm * B1.y); acc = fmaf(hs[5], C1.y, acc);
            hs[6] = fmaf(hs[6], dAv, cbm * B1.z); acc = fmaf(hs[6], C1.z, acc);
            hs[7] = fmaf(hs[7], dAv, cbm * B1.w); acc = fmaf(hs[7], C1.w, acc);
            acc += __shfl_xor_sync(0xffffffffu, acc, 1);
            acc += __shfl_xor_sync(0xffffffffu, acc, 2);
            acc += __shfl_xor_sync(0xffffffffu, acc, 4);
            if (n_sub == 0)
                ybase[(size_t)t * DINNER] = acc + Dv * xv;
            int tn = t + SDEPTH;
            if (tn > SEQ - 1) tn = SEQ - 1;
            const float* row = base + (size_t)tn * CDIM;
            Bb[s][0] = *(const float4*)(row + boff);
            Bb[s][1] = *(const float4*)(row + boff + 4);
            Cb[s][0] = *(const float4*)(row + coff);
            Cb[s][1] = *(const float4*)(row + coff + 4);
            xb[s] = row[xoff];
            db[s] = dbase[(size_t)tn * NHEADS];
        }
    }
}

// ---------------- final norms ----------------
__global__ void __launch_bounds__(256) finalnorm_kernel(
    const float* __restrict__ rw, const float* __restrict__ lg, const float* __restrict__ lb) {
    int r = blockIdx.x, e = threadIdx.x;
    float v = g_x[(size_t)r * EMB + e];
    float ss = blockReduceSum(v * v);
    float xr = v * rsqrtf(ss * (1.f / EMB) + 1e-5f) * rw[e];
    float m = blockReduceSum(xr) * (1.f / EMB);
    float d = xr - m;
    float var = blockReduceSum(d * d) * (1.f / EMB);
    g_xn[(size_t)r * EMB + e] = d * rsqrtf(var + 1e-5f) * lg[e] + lb[e];
}

// ---------------- mlp2 ----------------
__global__ void __launch_bounds__(256) mlp2_kernel(
    const float* __restrict__ W2, const float* __restrict__ b2, float* __restrict__ out) {
    __shared__ float Ws[EMB * 5];
    __shared__ float bs[5];
    int tid = threadIdx.x;
    for (int i = tid; i < EMB * 5; i += 256) Ws[i] = W2[i];
    if (tid < 5) bs[tid] = b2[tid];
    __syncthreads();
    int warp = tid >> 5, lane = tid & 31;
    int tok = blockIdx.x * 8 + warp;
    float a0=0,a1=0,a2=0,a3=0,a4=0;
    for (int k = lane; k < EMB; k += 32) {
        float hv = g_h1[(size_t)tok * EMB + k];
        a0 = fmaf(hv, Ws[k * 5 + 0], a0);
        a1 = fmaf(hv, Ws[k * 5 + 1], a1);
        a2 = fmaf(hv, Ws[k * 5 + 2], a2);
        a3 = fmaf(hv, Ws[k * 5 + 3], a3);
        a4 = fmaf(hv, Ws[k * 5 + 4], a4);
    }
    #pragma unroll
    for (int o = 16; o; o >>= 1) {
        a0 += __shfl_xor_sync(0xffffffffu, a0, o);
        a1 += __shfl_xor_sync(0xffffffffu, a1, o);
        a2 += __shfl_xor_sync(0xffffffffu, a2, o);
        a3 += __shfl_xor_sync(0xffffffffu, a3, o);
        a4 += __shfl_xor_sync(0xffffffffu, a4, o);
    }
    if (lane == 0) {
        out[(size_t)tok * 5 + 0] = a0 + bs[0];
        out[(size_t)tok * 5 + 1] = a1 + bs[1];
        out[(size_t)tok * 5 + 2] = a2 + bs[2];
        out[(size_t)tok * 5 + 3] = a3 + bs[3];
        out[(size_t)tok * 5 + 4] = a4 + bs[4];
    }
}

// ---------------- host launcher ----------------
extern "C" void kernel_launch(void* const* d_in, const int* in_sizes, int n_in,
                              void* d_out, int out_size) {
    const float* feature     = (const float*)d_in[0];
    const float* w_avg       = (const float*)d_in[1];
    const float* inproj_ln_g = (const float*)d_in[2];
    const float* inproj_ln_b = (const float*)d_in[3];
    const float* inproj_W    = (const float*)d_in[4];
    const float* inproj_b    = (const float*)d_in[5];
    const float* rms_w       = (const float*)d_in[6];
    const float* m_inW       = (const float*)d_in[7];
    const float* m_convW     = (const float*)d_in[8];
    const float* m_convB     = (const float*)d_in[9];
    const float* m_dtb       = (const float*)d_in[10];
    const float* m_Alog      = (const float*)d_in[11];
    const float* m_D         = (const float*)d_in[12];
    const float* m_gnw       = (const float*)d_in[13];
    const float* m_outW      = (const float*)d_in[14];
    const float* norm_w      = (const float*)d_in[15];
    const float* mlp_ln_g    = (const float*)d_in[16];
    const float* mlp_ln_b    = (const float*)d_in[17];
    const float* mlp_W1      = (const float*)d_in[18];
    const float* mlp_b1      = (const float*)d_in[19];
    const float* mlp_W2      = (const float*)d_in[20];
    const float* mlp_b2      = (const float*)d_in[21];
    float* out = (float*)d_out;

    float *xn, *x, *z, *y, *h1;
    cudaGetSymbolAddress((void**)&xn, g_xn);
    cudaGetSymbolAddress((void**)&x,  g_x);
    cudaGetSymbolAddress((void**)&z,  g_z);
    cudaGetSymbolAddress((void**)&y,  g_y);
    cudaGetSymbolAddress((void**)&h1, g_h1);

    cudaFuncSetAttribute(tgemm2_kernel<0,1>, cudaFuncAttributeMaxDynamicSharedMemorySize, TG2_SMEM);
    cudaFuncSetAttribute(tgemm2_kernel<1,0>, cudaFuncAttributeMaxDynamicSharedMemorySize, TG2_SMEM);
    cudaFuncSetAttribute(tgemm2_kernel<2,3>, cudaFuncAttributeMaxDynamicSharedMemorySize, TG2_SMEM);
    cudaFuncSetAttribute(tgemm2_kernel<0,2>, cudaFuncAttributeMaxDynamicSharedMemorySize, TG2_SMEM);

    softmax_kernel<<<1, 32>>>(w_avg, NFEAT);
    avg_ln_kernel<<<TOK, 128>>>(feature, inproj_ln_g, inproj_ln_b);

    // x = LN(feat_avg) @ inproj_W + inproj_b     (16384x128 @ 128x256)
    tgemm2_kernel<0,1><<<dim3((EMB + 127) / 128, TOK / 128), 256, TG2_SMEM>>>(
        xn, nullptr, inproj_W, nullptr, inproj_b, nullptr, x, TOK, EMB, DMODEL);

    for (int i = 0; i < NLAYERS; ++i) {
        // zxbcdt = rmsnorm(x, rms_w[i]) @ m_inW[i]   (fused pre-norm; 16384x256 @ 256x1160)
        tgemm2_kernel<1,0><<<dim3((DIP + 127) / 128, TOK / 128), 256, TG2_SMEM>>>(
            x, nullptr, m_inW + (size_t)i * EMB * DIP, rms_w + (size_t)i * EMB,
            nullptr, nullptr, z, TOK, DIP, EMB);
        conv_kernel<<<TOK, 256>>>(m_convW + (size_t)i * CDIM * DCONV,
                                  m_convB + (size_t)i * CDIM,
                                  m_dtb + i * NHEADS, m_Alog + i * NHEADS);
        scan_kernel<<<dim3(2, NHEADS, BATCH), 256>>>(m_D + i * NHEADS);
        // x = rmsnorm(y*silu(z), gnw) @ m_outW[i] + x  (fused gate; 16384x512 @ 512x256)
        tgemm2_kernel<2,3><<<dim3((EMB + 127) / 128, TOK / 128), 256, TG2_SMEM>>>(
            y, z, m_outW + (size_t)i * DINNER * EMB, m_gnw + (size_t)i * DINNER,
            nullptr, x, x, TOK, EMB, DINNER);
    }

    finalnorm_kernel<<<TOK, 256>>>(norm_w, mlp_ln_g, mlp_ln_b);
    // h1 = gelu(xn @ W1 + b1)                    (16384x256 @ 256x256)
    tgemm2_kernel<0,2><<<dim3((EMB + 127) / 128, TOK / 128), 256, TG2_SMEM>>>(
        xn, nullptr, mlp_W1, nullptr, mlp_b1, nullptr, h1, TOK, EMB, EMB);
    mlp2_kernel<<<TOK / 8, 256>>>(mlp_W2, mlp_b2, out);
}

// round 9
// speedup vs baseline: 1.0066x; 1.0066x over previous
#include <cuda_runtime.h>
#include <cuda_bf16.h>
#include <math.h>

// ---------------- problem constants ----------------
#define BATCH   8
#define SEQ     2048
#define TOK     (BATCH*SEQ)      // 16384
#define DMODEL  128
#define EMB     256
#define NLAYERS 3
#define NHEADS  8
#define HEADDIM 64
#define DSTATE  64
#define DCONV   4
#define DINNER  (NHEADS*HEADDIM)             // 512
#define DIP     (2*DINNER + 2*DSTATE + NHEADS) // 1160
#define CDIM    (DINNER + 2*DSTATE)          // 640
#define NFEAT   15

// ---------------- device scratch ----------------
__device__ float g_w[16];
__device__ float g_xn[TOK*EMB];
__device__ float g_x [TOK*EMB];
__device__ float g_z [TOK*DIP];
__device__ float g_xbc[TOK*CDIM];
__device__ float2 g_dtA[TOK*NHEADS];   // (.x = dt, .y = dA)
__device__ float g_y [TOK*DINNER];
__device__ float g_h1[TOK*EMB];

// ---------------- helpers ----------------
__device__ __forceinline__ float blockReduceSum(float v) {
    __shared__ float red[32];
    int lane = threadIdx.x & 31;
    int wid  = threadIdx.x >> 5;
    int nw   = (blockDim.x + 31) >> 5;
    #pragma unroll
    for (int o = 16; o; o >>= 1) v += __shfl_xor_sync(0xffffffffu, v, o);
    __syncthreads();
    if (lane == 0) red[wid] = v;
    __syncthreads();
    float tot = 0.f;
    for (int i = 0; i < nw; ++i) tot += red[i];
    return tot;
}

__device__ __forceinline__ float siluf(float x) { return x / (1.f + expf(-x)); }

__device__ __forceinline__ void mma_tf32(float* d, const unsigned* a, unsigned b0, unsigned b1) {
    asm volatile(
        "mma.sync.aligned.m16n8k8.row.col.f32.tf32.tf32.f32 "
        "{%0,%1,%2,%3},{%4,%5,%6,%7},{%8,%9},{%0,%1,%2,%3};\n"
        : "+f"(d[0]), "+f"(d[1]), "+f"(d[2]), "+f"(d[3])
        : "r"(a[0]), "r"(a[1]), "r"(a[2]), "r"(a[3]), "r"(b0), "r"(b1));
}

__device__ __forceinline__ void tf32_split(float x, unsigned& hi, unsigned& lo) {
    unsigned h;
    asm("cvt.rna.tf32.f32 %0, %1;\n" : "=r"(h) : "f"(x));
    float r = x - __uint_as_float(h);
    unsigned l;
    asm("cvt.rna.tf32.f32 %0, %1;\n" : "=r"(l) : "f"(r));
    hi = h; lo = l;
}

// ---------------- K0: softmax of w_avg ----------------
__global__ void softmax_kernel(const float* __restrict__ wa, int n) {
    if (threadIdx.x == 0) {
        float mx = -1e30f;
        for (int i = 0; i < n; ++i) mx = fmaxf(mx, wa[i]);
        float s = 0.f;
        for (int i = 0; i < n; ++i) { float e = expf(wa[i] - mx); g_w[i] = e; s += e; }
        float inv = 1.f / s;
        for (int i = 0; i < n; ++i) g_w[i] *= inv;
    }
}

// ---------------- K1: weighted feature average + layernorm(128) ----------------
__global__ void __launch_bounds__(128) avg_ln_kernel(
    const float* __restrict__ feat, const float* __restrict__ lg,
    const float* __restrict__ lb) {
    int r = blockIdx.x;
    int d = threadIdx.x;
    float acc = 0.f;
    #pragma unroll
    for (int f = 0; f < NFEAT; ++f)
        acc = fmaf(g_w[f], feat[((size_t)f * TOK + r) * DMODEL + d], acc);
    float m = blockReduceSum(acc) * (1.f / DMODEL);
    float dv = acc - m;
    float var = blockReduceSum(dv * dv) * (1.f / DMODEL);
    g_xn[(size_t)r * DMODEL + d] = dv * rsqrtf(var + 1e-5f) * lg[d] + lb[d];
}

// ---------------- 3xTF32 GEMM v2: split-at-STS, fused row-norm pre-ops ----------------
// C = epi( sc_row * (pre(A)(MxK) @ W(KxN)) )
// PRE: 0 = plain A
//      1 = rmsnorm fusion: store x*prew[k], sc_row = rsqrt(mean x^2 + eps)
//      2 = gate fusion:    g = y*silu(z); store g*prew[k], sc_row = rsqrt(mean g^2 + eps)
// EPI: 0=none 1=+bias 2=gelu(x+bias) 3=+residual
// Tiles BM=128 BN=128 BK=32; 8 warps (4m x 2n); warp tile 32x64.
// Smem planes hold (hi,lo) tf32 pairs as float2; LDS.64 fetches both terms at once.
#define ASF2 36
#define BSF2 132
#define ASF2_ELEMS (128*ASF2)
#define BSF2_ELEMS (32*BSF2)
#define TG2_SMEM ((2*ASF2_ELEMS + 2*BSF2_ELEMS)*8)

template<int PRE, int EPI>
__global__ void __launch_bounds__(256, 1) tgemm2_kernel(
    const float* __restrict__ A, const float* __restrict__ Az,
    const float* __restrict__ W, const float* __restrict__ prew,
    const float* __restrict__ bias, const float* __restrict__ res,
    float* __restrict__ C, int M, int N, int K)
{
    extern __shared__ float2 sm2[];
    float2* As[2] = { sm2, sm2 + ASF2_ELEMS };
    float2* Bs[2] = { sm2 + 2*ASF2_ELEMS, sm2 + 2*ASF2_ELEMS + BSF2_ELEMS };
    __shared__ float s_sc[128];

    int tid = threadIdx.x;
    int n0 = blockIdx.x * 128;
    int m0 = blockIdx.y * 128;
    int wid = tid >> 5, lane = tid & 31;
    int wm = wid >> 1, wn = wid & 1;
    int m0w = wm * 32, n0w = wn * 64;
    int g = lane >> 2, q = lane & 3;

    float acc[2][8][4];
    #pragma unroll
    for (int mi = 0; mi < 2; ++mi)
        #pragma unroll
        for (int ni = 0; ni < 8; ++ni)
            #pragma unroll
            for (int c = 0; c < 4; ++c) acc[mi][ni][c] = 0.f;

    int ar = tid >> 1, ak = (tid & 1) * 16;    // A: 2 threads per row, 16 k each
    int bk = tid & 31, bn = (tid >> 5) * 16;   // B: 1 k-row per lane-id, 16 n per warp

    float row_ss = 0.f;
    float4 rA[4], rZ[4], rB[4];

    auto loadG = [&](int k0) {
        const float* ag = A + (size_t)(m0 + ar) * K + k0 + ak;
        #pragma unroll
        for (int j = 0; j < 4; ++j) rA[j] = *(const float4*)(ag + j * 4);
        if (PRE == 2) {
            const float* zg = Az + (size_t)(m0 + ar) * DIP + k0 + ak;
            #pragma unroll
            for (int j = 0; j < 4; ++j) rZ[j] = *(const float4*)(zg + j * 4);
        }
        const float* bg = W + (size_t)(k0 + bk) * N + n0 + bn;
        #pragma unroll
        for (int j = 0; j < 4; ++j) {
            int col = n0 + bn + j * 4;
            rB[j] = (col < N) ? *(const float4*)(bg + j * 4)
                              : make_float4(0.f, 0.f, 0.f, 0.f);
        }
    };

    auto sts = [&](int buf, int k0) {
        float2* ad = As[buf] + ar * ASF2 + ak;
        #pragma unroll
        for (int j = 0; j < 4; ++j) {
            float v[4] = { rA[j].x, rA[j].y, rA[j].z, rA[j].w };
            if (PRE == 1) {
                const float* wv = prew + k0 + ak + j * 4;
                #pragma unroll
                for (int e = 0; e < 4; ++e) {
                    float x = v[e];
                    row_ss = fmaf(x, x, row_ss);
                    v[e] = x * wv[e];
                }
            } else if (PRE == 2) {
                float zz[4] = { rZ[j].x, rZ[j].y, rZ[j].z, rZ[j].w };
                const float* wv = prew + k0 + ak + j * 4;
                #pragma unroll
                for (int e = 0; e < 4; ++e) {
                    float gg = v[e] * siluf(zz[e]);
                    row_ss = fmaf(gg, gg, row_ss);
                    v[e] = gg * wv[e];
                }
            }
            unsigned h[4], l[4];
            #pragma unroll
            for (int e = 0; e < 4; ++e) tf32_split(v[e], h[e], l[e]);
            uint4* dst = (uint4*)(ad + j * 4);
            dst[0] = make_uint4(h[0], l[0], h[1], l[1]);
            dst[1] = make_uint4(h[2], l[2], h[3], l[3]);
        }
        float2* bd = Bs[buf] + bk * BSF2 + bn;
        #pragma unroll
        for (int j = 0; j < 4; ++j) {
            float v[4] = { rB[j].x, rB[j].y, rB[j].z, rB[j].w };
            unsigned h[4], l[4];
            #pragma unroll
            for (int e = 0; e < 4; ++e) tf32_split(v[e], h[e], l[e]);
            uint4* dst = (uint4*)(bd + j * 4);
            dst[0] = make_uint4(h[0], l[0], h[1], l[1]);
            dst[1] = make_uint4(h[2], l[2], h[3], l[3]);
        }
    };

    int nk = K >> 5;
    loadG(0);
    sts(0, 0);
    loadG(32);
    __syncthreads();

    for (int kb = 0; kb < nk; ++kb) {
        const float2* Ab = As[kb & 1];
        const float2* Bb = Bs[kb & 1];
        #pragma unroll
        for (int ks = 0; ks < 4; ++ks) {
            int kq = ks * 8;
            unsigned ah[2][4], al[2][4];
            #pragma unroll
            for (int mi = 0; mi < 2; ++mi) {
                const float2* ab = Ab + (m0w + mi * 16 + g) * ASF2 + kq + q;
                float2 t0 = ab[0];
                float2 t1 = ab[8 * ASF2];
                float2 t2 = ab[4];
                float2 t3 = ab[8 * ASF2 + 4];
                ah[mi][0] = __float_as_uint(t0.x); al[mi][0] = __float_as_uint(t0.y);
                ah[mi][1] = __float_as_uint(t1.x); al[mi][1] = __float_as_uint(t1.y);
                ah[mi][2] = __float_as_uint(t2.x); al[mi][2] = __float_as_uint(t2.y);
                ah[mi][3] = __float_as_uint(t3.x); al[mi][3] = __float_as_uint(t3.y);
            }
            #pragma unroll
            for (int ni = 0; ni < 8; ++ni) {
                const float2* bb = Bb + (kq + q) * BSF2 + n0w + ni * 8 + g;
                float2 s0 = bb[0];
                float2 s1 = bb[4 * BSF2];
                unsigned bh0 = __float_as_uint(s0.x), bl0 = __float_as_uint(s0.y);
                unsigned bh1 = __float_as_uint(s1.x), bl1 = __float_as_uint(s1.y);
                mma_tf32(acc[0][ni], al[0], bh0, bh1);
                mma_tf32(acc[1][ni], al[1], bh0, bh1);
                mma_tf32(acc[0][ni], ah[0], bl0, bl1);
                mma_tf32(acc[1][ni], ah[1], bl0, bl1);
                mma_tf32(acc[0][ni], ah[0], bh0, bh1);
                mma_tf32(acc[1][ni], ah[1], bh0, bh1);
            }
        }
        if (kb + 1 < nk) {
            __syncthreads();
            sts((kb + 1) & 1, (kb + 1) * 32);
            if (kb + 2 < nk) loadG((kb + 2) * 32);
            __syncthreads();
        }
    }

    if (PRE > 0) {
        float tot = row_ss + __shfl_xor_sync(0xffffffffu, row_ss, 1);
        if ((tid & 1) == 0) s_sc[ar] = rsqrtf(tot * (1.f / (float)K) + 1e-5f);
        __syncthreads();
    }

    #pragma unroll
    for (int mi = 0; mi < 2; ++mi) {
        #pragma unroll
        for (int ni = 0; ni < 8; ++ni) {
            int col = n0 + n0w + ni * 8 + 2 * q;
            if (col >= N) continue;
            #pragma unroll
            for (int half = 0; half < 2; ++half) {
                int lrow = m0w + mi * 16 + g + half * 8;
                int row = m0 + lrow;
                float sc = (PRE > 0) ? s_sc[lrow] : 1.f;
                float v0 = sc * acc[mi][ni][half * 2 + 0];
                float v1 = sc * acc[mi][ni][half * 2 + 1];
                if (EPI == 1) { v0 += bias[col]; v1 += bias[col + 1]; }
                else if (EPI == 2) {
                    v0 += bias[col]; v1 += bias[col + 1];
                    v0 = 0.5f * v0 * (1.f + erff(v0 * 0.70710678118654752f));
                    v1 = 0.5f * v1 * (1.f + erff(v1 * 0.70710678118654752f));
                } else if (EPI == 3) {
                    const float* rp = res + (size_t)row * N + col;
                    v0 += rp[0]; v1 += rp[1];
                }
                *(float2*)(C + (size_t)row * N + col) = make_float2(v0, v1);
            }
        }
    }
}

// ---------------- conv (depthwise causal, DCONV=4) + silu, plus packed dt/dA ----------------
__global__ void __launch_bounds__(256) conv_kernel(
    const float* __restrict__ cw, const float* __restrict__ cb,
    const float* __restrict__ dtb, const float* __restrict__ alog) {
    int r = blockIdx.x;
    int b = r >> 11, t = r & 2047;
    for (int c = threadIdx.x; c < CDIM; c += 256) {
        float acc = cb[c];
        #pragma unroll
        for (int k = 0; k < DCONV; ++k) {
            int tt = t - (DCONV - 1) + k;
            if (tt >= 0)
                acc = fmaf(g_z[((size_t)(b * SEQ + tt)) * DIP + DINNER + c], cw[c * DCONV + k], acc);
        }
        g_xbc[(size_t)r * CDIM + c] = siluf(acc);
    }
    if (threadIdx.x < NHEADS) {
        int hh = threadIdx.x;
        float v = g_z[(size_t)r * DIP + (DIP - NHEADS) + hh] + dtb[hh];
        float dt = (v > 20.f) ? v : log1pf(expf(v));
        float dA = expf(-dt * expf(alog[hh]));
        g_dtA[r * NHEADS + hh] = make_float2(dt, dA);
    }
}

// ---------------- selective scan: warp-autonomous register version (R5, passing) ----------------
#define SDEPTH 4

__global__ void __launch_bounds__(256) scan_kernel(const float* __restrict__ Dp) {
    int pz = blockIdx.x;
    int h  = blockIdx.y;
    int b  = blockIdx.z;
    int tid = threadIdx.x;
    int w = tid >> 5, lane = tid & 31;
    int p_sub = lane >> 3;
    int n_sub = lane & 7;
    int p = pz * 32 + w * 4 + p_sub;

    const float* base = g_xbc + (size_t)b * SEQ * CDIM;
    const float2* dbase = g_dtA + (size_t)b * SEQ * NHEADS + h;
    float* ybase = g_y + (size_t)b * SEQ * DINNER + h * HEADDIM + p;
    float Dv = Dp[h];

    float hs[8];
    #pragma unroll
    for (int j = 0; j < 8; ++j) hs[j] = 0.f;

    float4 Bb[SDEPTH][2], Cb[SDEPTH][2];
    float  xb[SDEPTH];
    float2 db[SDEPTH];

    const int boff = DINNER + n_sub * 8;
    const int coff = DINNER + DSTATE + n_sub * 8;
    const int xoff = h * HEADDIM + p;

    #pragma unroll
    for (int s = 0; s < SDEPTH; ++s) {
        const float* row = base + (size_t)s * CDIM;
        Bb[s][0] = *(const float4*)(row + boff);
        Bb[s][1] = *(const float4*)(row + boff + 4);
        Cb[s][0] = *(const float4*)(row + coff);
        Cb[s][1] = *(const float4*)(row + coff + 4);
        xb[s] = row[xoff];
        db[s] = dbase[(size_t)s * NHEADS];
    }

    for (int t0 = 0; t0 < SEQ; t0 += SDEPTH) {
        #pragma unroll
        for (int s = 0; s < SDEPTH; ++s) {
            int t = t0 + s;
            float dtv = db[s].x, dAv = db[s].y;
            float xv = xb[s];
            float cbm = dtv * xv;
            float4 B0 = Bb[s][0], B1 = Bb[s][1];
            float4 C0 = Cb[s][0], C1 = Cb[s][1];
            float acc;
            hs[0] = fmaf(hs[0], dAv, cbm * B0.x); acc = hs[0] * C0.x;
            hs[1] = fmaf(hs[1], dAv, cbm * B0.y); acc = fmaf(hs[1], C0.y, acc);
            hs[2] = fmaf(hs[2], dAv, cbm * B0.z); acc = fmaf(hs[2], C0.z, acc);
            hs[3] = fmaf(hs[3], dAv, cbm * B0.w); acc = fmaf(hs[3], C0.w, acc);
            hs[4] = fmaf(hs[4], dAv, cbm * B1.x); acc = fmaf(hs[4], C1.x, acc);
            hs[5] = fmaf(hs[5], dAv, cbm * B1.y); acc = fmaf(hs[5], C1.y, acc);
            hs[6] = fmaf(hs[6], dAv, cbm * B1.z); acc = fmaf(hs[6], C1.z, acc);
            hs[7] = fmaf(hs[7], dAv, cbm * B1.w); acc = fmaf(hs[7], C1.w, acc);
            acc += __shfl_xor_sync(0xffffffffu, acc, 1);
            acc += __shfl_xor_sync(0xffffffffu, acc, 2);
            acc += __shfl_xor_sync(0xffffffffu, acc, 4);
            if (n_sub == 0)
                ybase[(size_t)t * DINNER] = acc + Dv * xv;
            int tn = t + SDEPTH;
            if (tn > SEQ - 1) tn = SEQ - 1;
            const float* row = base + (size_t)tn * CDIM;
            Bb[s][0] = *(const float4*)(row + boff);
            Bb[s][1] = *(const float4*)(row + boff + 4);
            Cb[s][0] = *(const float4*)(row + coff);
            Cb[s][1] = *(const float4*)(row + coff + 4);
            xb[s] = row[xoff];
            db[s] = dbase[(size_t)tn * NHEADS];
        }
    }
}

// ---------------- final norms ----------------
__global__ void __launch_bounds__(256) finalnorm_kernel(
    const float* __restrict__ rw, const float* __restrict__ lg, const float* __restrict__ lb) {
    int r = blockIdx.x, e = threadIdx.x;
    float v = g_x[(size_t)r * EMB + e];
    float ss = blockReduceSum(v * v);
    float xr = v * rsqrtf(ss * (1.f / EMB) + 1e-5f) * rw[e];
    float m = blockReduceSum(xr) * (1.f / EMB);
    float d = xr - m;
    float var = blockReduceSum(d * d) * (1.f / EMB);
    g_xn[(size_t)r * EMB + e] = d * rsqrtf(var + 1e-5f) * lg[e] + lb[e];
}

// ---------------- mlp2 ----------------
__global__ void __launch_bounds__(256) mlp2_kernel(
    const float* __restrict__ W2, const float* __restrict__ b2, float* __restrict__ out) {
    __shared__ float Ws[EMB * 5];
    __shared__ float bs[5];
    int tid = threadIdx.x;
    for (int i = tid; i < EMB * 5; i += 256) Ws[i] = W2[i];
    if (tid < 5) bs[tid] = b2[tid];
    __syncthreads();
    int warp = tid >> 5, lane = tid & 31;
    int tok = blockIdx.x * 8 + warp;
    float a0=0,a1=0,a2=0,a3=0,a4=0;
    for (int k = lane; k < EMB; k += 32) {
        float hv = g_h1[(size_t)tok * EMB + k];
        a0 = fmaf(hv, Ws[k * 5 + 0], a0);
        a1 = fmaf(hv, Ws[k * 5 + 1], a1);
        a2 = fmaf(hv, Ws[k * 5 + 2], a2);
        a3 = fmaf(hv, Ws[k * 5 + 3], a3);
        a4 = fmaf(hv, Ws[k * 5 + 4], a4);
    }
    #pragma unroll
    for (int o = 16; o; o >>= 1) {
        a0 += __shfl_xor_sync(0xffffffffu, a0, o);
        a1 += __shfl_xor_sync(0xffffffffu, a1, o);
        a2 += __shfl_xor_sync(0xffffffffu, a2, o);
        a3 += __shfl_xor_sync(0xffffffffu, a3, o);
        a4 += __shfl_xor_sync(0xffffffffu, a4, o);
    }
    if (lane == 0) {
        out[(size_t)tok * 5 + 0] = a0 + bs[0];
        out[(size_t)tok * 5 + 1] = a1 + bs[1];
        out[(size_t)tok * 5 + 2] = a2 + bs[2];
        out[(size_t)tok * 5 + 3] = a3 + bs[3];
        out[(size_t)tok * 5 + 4] = a4 + bs[4];
    }
}

// ---------------- host launcher ----------------
extern "C" void kernel_launch(void* const* d_in, const int* in_sizes, int n_in,
                              void* d_out, int out_size) {
    const float* feature     = (const float*)d_in[0];
    const float* w_avg       = (const float*)d_in[1];
    const float* inproj_ln_g = (const float*)d_in[2];
    const float* inproj_ln_b = (const float*)d_in[3];
    const float* inproj_W    = (const float*)d_in[4];
    const float* inproj_b    = (const float*)d_in[5];
    const float* rms_w       = (const float*)d_in[6];
    const float* m_inW       = (const float*)d_in[7];
    const float* m_convW     = (const float*)d_in[8];
    const float* m_convB     = (const float*)d_in[9];
    const float* m_dtb       = (const float*)d_in[10];
    const float* m_Alog      = (const float*)d_in[11];
    const float* m_D         = (const float*)d_in[12];
    const float* m_gnw       = (const float*)d_in[13];
    const float* m_outW      = (const float*)d_in[14];
    const float* norm_w      = (const float*)d_in[15];
    const float* mlp_ln_g    = (const float*)d_in[16];
    const float* mlp_ln_b    = (const float*)d_in[17];
    const float* mlp_W1      = (const float*)d_in[18];
    const float* mlp_b1      = (const float*)d_in[19];
    const float* mlp_W2      = (const float*)d_in[20];
    const float* mlp_b2      = (const float*)d_in[21];
    float* out = (float*)d_out;

    float *xn, *x, *z, *y, *h1;
    cudaGetSymbolAddress((void**)&xn, g_xn);
    cudaGetSymbolAddress((void**)&x,  g_x);
    cudaGetSymbolAddress((void**)&z,  g_z);
    cudaGetSymbolAddress((void**)&y,  g_y);
    cudaGetSymbolAddress((void**)&h1, g_h1);

    cudaFuncSetAttribute(tgemm2_kernel<0,1>, cudaFuncAttributeMaxDynamicSharedMemorySize, TG2_SMEM);
    cudaFuncSetAttribute(tgemm2_kernel<1,0>, cudaFuncAttributeMaxDynamicSharedMemorySize, TG2_SMEM);
    cudaFuncSetAttribute(tgemm2_kernel<2,3>, cudaFuncAttributeMaxDynamicSharedMemorySize, TG2_SMEM);
    cudaFuncSetAttribute(tgemm2_kernel<0,2>, cudaFuncAttributeMaxDynamicSharedMemorySize, TG2_SMEM);

    softmax_kernel<<<1, 32>>>(w_avg, NFEAT);
    avg_ln_kernel<<<TOK, 128>>>(feature, inproj_ln_g, inproj_ln_b);

    // x = LN(feat_avg) @ inproj_W + inproj_b     (16384x128 @ 128x256)
    tgemm2_kernel<0,1><<<dim3((EMB + 127) / 128, TOK / 128), 256, TG2_SMEM>>>(
        xn, nullptr, inproj_W, nullptr, inproj_b, nullptr, x, TOK, EMB, DMODEL);

    for (int i = 0; i < NLAYERS; ++i) {
        // zxbcdt = rmsnorm(x, rms_w[i]) @ m_inW[i]   (fused pre-norm; 16384x256 @ 256x1160)
        tgemm2_kernel<1,0><<<dim3((DIP + 127) / 128, TOK / 128), 256, TG2_SMEM>>>(
            x, nullptr, m_inW + (size_t)i * EMB * DIP, rms_w + (size_t)i * EMB,
            nullptr, nullptr, z, TOK, DIP, EMB);
        conv_kernel<<<TOK, 256>>>(m_convW + (size_t)i * CDIM * DCONV,
                                  m_convB + (size_t)i * CDIM,
                                  m_dtb + i * NHEADS, m_Alog + i * NHEADS);
        scan_kernel<<<dim3(2, NHEADS, BATCH), 256>>>(m_D + i * NHEADS);
        // x = rmsnorm(y*silu(z), gnw) @ m_outW[i] + x  (fused gate; 16384x512 @ 512x256)
        tgemm2_kernel<2,3><<<dim3((EMB + 127) / 128, TOK / 128), 256, TG2_SMEM>>>(
            y, z, m_outW + (size_t)i * DINNER * EMB, m_gnw + (size_t)i * DINNER,
            nullptr, x, x, TOK, EMB, DINNER);
    }

    finalnorm_kernel<<<TOK, 256>>>(norm_w, mlp_ln_g, mlp_ln_b);
    // h1 = gelu(xn @ W1 + b1)                    (16384x256 @ 256x256)
    tgemm2_kernel<0,2><<<dim3((EMB + 127) / 128, TOK / 128), 256, TG2_SMEM>>>(
        xn, nullptr, mlp_W1, nullptr, mlp_b1, nullptr, h1, TOK, EMB, EMB);
    mlp2_kernel<<<TOK / 8, 256>>>(mlp_W2, mlp_b2, out);
}